// round 13
// baseline (speedup 1.0000x reference)
#include <cuda_runtime.h>
#include <cuda_bf16.h>
#include <cstddef>

#define ROWS   128
#define T      30
#define OUT_T  26
#define NPAIRS 8256
#define NTHREADS 512
#define NWARPS   16
#define UNITS    320        // 10 tiles * 32 i-iterations
#define UPW      (UNITS / NWARPS)   // 20 units per warp

#define XS_STRIDE 36        // 144 B rows: 16B-aligned for float4 broadcast loads
// float2 staging stride 37 (≡5 mod 16): STS.64 and gather LDS.64 both at the
// 2-lanes-per-8B-bank floor (verified by R12's L1 drop 70.5% -> 56.4%).
#define STG2_STRIDE 37
#define STG2_WORDS (13 * STG2_STRIDE)   // 481 float2 per warp

__device__ __forceinline__ int pair_offset(int i) {
    return i * ROWS - (i * (i - 1)) / 2;
}

__device__ __forceinline__ int div26(int w) {   // exact floor(w/26) for 0<=w<832
    return (w * 10083) >> 18;
}

__global__ __launch_bounds__(NTHREADS, 1)
void ts_cov_kernel(const float* __restrict__ in, float* __restrict__ out) {
    const int batch = blockIdx.x;

    __shared__ float xs[ROWS * XS_STRIDE];            // 18432 B
    __shared__ float2 stage2[NWARPS * STG2_WORDS];    // 61568 B

    float* stage_f = (float*)stage2;

    // ---- Stage raw input (coalesced) ----
    const float* gin = in + (size_t)batch * (ROWS * T);
    for (int idx = threadIdx.x; idx < ROWS * T; idx += NTHREADS)
        stage_f[idx] = gin[idx];
    __syncthreads();

    // ---- Per-row normalization (population std) ----
    if (threadIdx.x < ROWS) {
        const int r = threadIdx.x;
        float s = 0.f;
#pragma unroll
        for (int t = 0; t < T; t++) s += stage_f[r * T + t];
        const float mean = s * (1.0f / T);
        float v = 0.f;
#pragma unroll
        for (int t = 0; t < T; t++) {
            float c = stage_f[r * T + t] - mean;
            v += c * c;
        }
        const float inv = rsqrtf(v * (1.0f / T));
#pragma unroll
        for (int t = 0; t < T; t++)
            xs[r * XS_STRIDE + t] = (stage_f[r * T + t] - mean) * inv;
    }
    __syncthreads();   // xs ready; stage2[] reused as per-warp staging

    const int wid  = threadIdx.x >> 5;
    const int lane = threadIdx.x & 31;
    float2* sw2 = stage2 + wid * STG2_WORDS;
    float* gout = out + (size_t)batch * ((size_t)NPAIRS * OUT_T);

    const int uA = wid * UPW;
    const int uB = uA + UPW;

    for (int tile = (uA >> 5); tile <= ((uB - 1) >> 5); ++tile) {
        // tile -> (jb, is), triangular enumeration with is <= jb
        const int jb = (tile >= 6) ? 3 : (tile >= 3) ? 2 : (tile >= 1) ? 1 : 0;
        const int is = tile - (jb * (jb + 1)) / 2;
        const int j0 = jb * 32;

        // b row (j0+lane) register-resident for this tile (float4 loads)
        float b[T];
        {
            const float4* bp = (const float4*)(xs + (j0 + lane) * XS_STRIDE);
#pragma unroll
            for (int m = 0; m < 7; m++) {
                float4 v4 = bp[m];
                b[m * 4 + 0] = v4.x; b[m * 4 + 1] = v4.y;
                b[m * 4 + 2] = v4.z; b[m * 4 + 3] = v4.w;
            }
            float2 v2 = *(const float2*)(xs + (j0 + lane) * XS_STRIDE + 28);
            b[28] = v2.x; b[29] = v2.y;
        }

        const int loU = max(uA, tile * 32);
        const int hiU = min(uB, tile * 32 + 32);

        for (int u = loU; u < hiU; ++u) {
            const int i = is * 32 + (u - tile * 32);

            // Broadcast-load row i (8 wavefronts), form products
            float p[T];
            {
                const float4* ap = (const float4*)(xs + i * XS_STRIDE);
#pragma unroll
                for (int m = 0; m < 7; m++) {
                    float4 v4 = ap[m];
                    p[m * 4 + 0] = v4.x * b[m * 4 + 0];
                    p[m * 4 + 1] = v4.y * b[m * 4 + 1];
                    p[m * 4 + 2] = v4.z * b[m * 4 + 2];
                    p[m * 4 + 3] = v4.w * b[m * 4 + 3];
                }
                float2 v2 = *(const float2*)(xs + i * XS_STRIDE + 28);
                p[28] = v2.x * b[28];
                p[29] = v2.y * b[29];
            }

            // Serial sliding-window recurrence (cheap: 2 FADD per output),
            // staged as float2 pairs: sw2[kk*37 + lane] = (res[2kk], res[2kk+1]).
            // Transition k-1 -> k: s += p[k+4] - p[k-1].
            {
                float s = p[0] + p[1] + p[2] + p[3] + p[4];
                float e0 = s * 0.2f;            // res[0]
                s += p[5] - p[0];               // k = 1
                sw2[lane] = make_float2(e0, s * 0.2f);
#pragma unroll
                for (int kk = 1; kk < 13; kk++) {
                    s += p[2 * kk + 4] - p[2 * kk - 1];   // k = 2kk
                    e0 = s * 0.2f;
                    s += p[2 * kk + 5] - p[2 * kk];       // k = 2kk+1
                    sw2[kk * STG2_STRIDE + lane] = make_float2(e0, s * 0.2f);
                }
            }
            __syncwarp();

            // Coalesced copy-out
            const int lo = (i > j0) ? (i - j0) : 0;
            const size_t p_start = (size_t)pair_offset(i) + (size_t)(j0 + lo - i);
            float* basep = gout + p_start * OUT_T;

            if (lo == 0) {
                // full tile: 416 float2; (w,w+1) w even -> sw2[k/2][q]
#pragma unroll
                for (int m = 0; m < 13; m++) {
                    const int w = 2 * (m * 32 + lane);
                    const int q = div26(w);
                    const int kk = (w - q * OUT_T) >> 1;
                    *(float2*)(basep + w) = sw2[kk * STG2_STRIDE + q];
                }
            } else {
                const int total = (32 - lo) * OUT_T;
#pragma unroll
                for (int m = 0; m < OUT_T; m++) {
                    const int w = m * 32 + lane;
                    if (w < total) {
                        const int q = div26(w);
                        const int k = w - q * OUT_T;
                        const float2 v = sw2[(k >> 1) * STG2_STRIDE + lo + q];
                        basep[w] = (k & 1) ? v.y : v.x;
                    }
                }
            }
            __syncwarp();   // protect sw2 before next iteration's STS
        }
    }
}

extern "C" void kernel_launch(void* const* d_in, const int* in_sizes, int n_in,
                              void* d_out, int out_size) {
    const float* in = (const float*)d_in[0];
    float* out = (float*)d_out;
    const int B = in_sizes[0] / (ROWS * T);
    ts_cov_kernel<<<B, NTHREADS>>>(in, out);
}

// round 14
// speedup vs baseline: 1.1692x; 1.1692x over previous
#include <cuda_runtime.h>
#include <cuda_bf16.h>
#include <cstddef>

#define ROWS   128
#define T      30
#define OUT_T  26
#define NPAIRS 8256
#define NTHREADS 640
#define NWARPS   20
#define UNITS    320        // 10 tiles * 32 i-iterations
#define UPW      (UNITS / NWARPS)   // 16 units per warp

#define XS_STRIDE 36        // 144 B rows: 16B-aligned for float4 broadcast loads
#define STG_STRIDE 33       // k-major staging stride (odd -> conflict-free)
#define STG_WORDS (OUT_T * STG_STRIDE)   // 858

__device__ __forceinline__ int pair_offset(int i) {
    return i * ROWS - (i * (i - 1)) / 2;
}

__device__ __forceinline__ int div26(int w) {   // exact floor(w/26) for 0<=w<832
    return (w * 10083) >> 18;
}

__global__ __launch_bounds__(NTHREADS, 1)
void ts_cov_kernel(const float* __restrict__ in, float* __restrict__ out) {
    const int batch = blockIdx.x;

    __shared__ float xs[ROWS * XS_STRIDE];          // 18432 B
    __shared__ float stage[NWARPS * STG_WORDS];     // 68640 B (doubles as raw staging)

    // ---- Stage raw input (coalesced) ----
    const float* gin = in + (size_t)batch * (ROWS * T);
    for (int idx = threadIdx.x; idx < ROWS * T; idx += NTHREADS)
        stage[idx] = gin[idx];
    __syncthreads();

    // ---- Per-row normalization (population std) ----
    if (threadIdx.x < ROWS) {
        const int r = threadIdx.x;
        float s = 0.f;
#pragma unroll
        for (int t = 0; t < T; t++) s += stage[r * T + t];
        const float mean = s * (1.0f / T);
        float v = 0.f;
#pragma unroll
        for (int t = 0; t < T; t++) {
            float c = stage[r * T + t] - mean;
            v += c * c;
        }
        const float inv = rsqrtf(v * (1.0f / T));
#pragma unroll
        for (int t = 0; t < T; t++)
            xs[r * XS_STRIDE + t] = (stage[r * T + t] - mean) * inv;
    }
    __syncthreads();   // xs ready; stage[] reused as per-warp staging

    const int wid  = threadIdx.x >> 5;
    const int lane = threadIdx.x & 31;
    float* sw = stage + wid * STG_WORDS;
    float* gout = out + (size_t)batch * ((size_t)NPAIRS * OUT_T);

    const int uA = wid * UPW;
    const int uB = uA + UPW;

    for (int tile = (uA >> 5); tile <= ((uB - 1) >> 5); ++tile) {
        // tile -> (jb, is), triangular enumeration with is <= jb
        const int jb = (tile >= 6) ? 3 : (tile >= 3) ? 2 : (tile >= 1) ? 1 : 0;
        const int is = tile - (jb * (jb + 1)) / 2;
        const int j0 = jb * 32;

        // b row (j0+lane) register-resident for this tile (float4 loads)
        float b[T];
        {
            const float4* bp = (const float4*)(xs + (j0 + lane) * XS_STRIDE);
#pragma unroll
            for (int m = 0; m < 7; m++) {
                float4 v4 = bp[m];
                b[m * 4 + 0] = v4.x; b[m * 4 + 1] = v4.y;
                b[m * 4 + 2] = v4.z; b[m * 4 + 3] = v4.w;
            }
            float2 v2 = *(const float2*)(xs + (j0 + lane) * XS_STRIDE + 28);
            b[28] = v2.x; b[29] = v2.y;
        }

        const int loU = max(uA, tile * 32);
        const int hiU = min(uB, tile * 32 + 32);

        for (int u = loU; u < hiU; ++u) {
            const int i = is * 32 + (u - tile * 32);
            const float4* ap = (const float4*)(xs + i * XS_STRIDE);

            // Ring-buffer sliding window (low register footprint):
            // ring[t%5] = p[t] = a[t]*b[t]; step k replaces slot (k+4)%5.
            float ring[5];
            float4 a4 = ap[0];                       // t = 0..3
            ring[0] = a4.x * b[0];
            ring[1] = a4.y * b[1];
            ring[2] = a4.z * b[2];
            ring[3] = a4.w * b[3];
            a4 = ap[1];                              // t = 4..7
            ring[4] = a4.x * b[4];

            float s = ring[0] + ring[1] + ring[2] + ring[3] + ring[4];
            sw[lane] = s * 0.2f;                     // res[0]
            {
                float pn;
                pn = a4.y * b[5]; s += pn - ring[0]; ring[0] = pn;   // k=1
                sw[1 * STG_STRIDE + lane] = s * 0.2f;
                pn = a4.z * b[6]; s += pn - ring[1]; ring[1] = pn;   // k=2
                sw[2 * STG_STRIDE + lane] = s * 0.2f;
                pn = a4.w * b[7]; s += pn - ring[2]; ring[2] = pn;   // k=3
                sw[3 * STG_STRIDE + lane] = s * 0.2f;
            }
#pragma unroll
            for (int c = 2; c < 8; c++) {            // k = 4..25
                a4 = ap[c];                          // t = 4c..4c+3
                const int k0 = 4 * c - 4;
                float pn;
                pn = a4.x * b[4 * c + 0]; s += pn - ring[(k0 + 4) % 5]; ring[(k0 + 4) % 5] = pn;
                sw[(k0 + 0) * STG_STRIDE + lane] = s * 0.2f;
                pn = a4.y * b[4 * c + 1]; s += pn - ring[(k0 + 5) % 5]; ring[(k0 + 5) % 5] = pn;
                sw[(k0 + 1) * STG_STRIDE + lane] = s * 0.2f;
                if (c < 7) {
                    pn = a4.z * b[4 * c + 2]; s += pn - ring[(k0 + 6) % 5]; ring[(k0 + 6) % 5] = pn;
                    sw[(k0 + 2) * STG_STRIDE + lane] = s * 0.2f;
                    pn = a4.w * b[4 * c + 3]; s += pn - ring[(k0 + 7) % 5]; ring[(k0 + 7) % 5] = pn;
                    sw[(k0 + 3) * STG_STRIDE + lane] = s * 0.2f;
                }
            }
            __syncwarp();

            // Coalesced copy-out (exact R11 pattern)
            const int lo = (i > j0) ? (i - j0) : 0;
            const size_t p_start = (size_t)pair_offset(i) + (size_t)(j0 + lo - i);
            float* basep = gout + p_start * OUT_T;

            if (lo == 0) {
                // full tile: 832 floats = 416 float2, 13 warp batches.
                // w even -> k = w-26q even <= 24, so (k,k+1) share pair q.
#pragma unroll
                for (int m = 0; m < 13; m++) {
                    const int w = 2 * (m * 32 + lane);
                    const int q = div26(w);
                    const int k = w - q * OUT_T;
                    float2 v = make_float2(sw[k * STG_STRIDE + q],
                                           sw[(k + 1) * STG_STRIDE + q]);
                    *(float2*)(basep + w) = v;
                }
            } else {
                const int total = (32 - lo) * OUT_T;
#pragma unroll
                for (int m = 0; m < OUT_T; m++) {
                    const int w = m * 32 + lane;
                    if (w < total) {
                        const int q = div26(w);
                        const int k = w - q * OUT_T;
                        basep[w] = sw[k * STG_STRIDE + lo + q];
                    }
                }
            }
            __syncwarp();   // protect sw before next iteration's STS
        }
    }
}

extern "C" void kernel_launch(void* const* d_in, const int* in_sizes, int n_in,
                              void* d_out, int out_size) {
    const float* in = (const float*)d_in[0];
    float* out = (float*)d_out;
    const int B = in_sizes[0] / (ROWS * T);
    ts_cov_kernel<<<B, NTHREADS>>>(in, out);
}